// round 2
// baseline (speedup 1.0000x reference)
#include <cuda_runtime.h>
#include <stdint.h>

// Problem constants
#define NMAX 20000
#define EMAX 160000
#define GMAX 64
#define DIN  36      // 32 emb + 4 feats
#define HID1 2048
#define HID2 1024

// ---------------- scratch (device globals, no runtime alloc) ----------------
__device__ float d_dinv[NMAX];
__device__ int   d_cnt[NMAX];
__device__ int   d_off[NMAX + 1];
__device__ int   d_cur[NMAX];
__device__ int   d_ssrc[EMAX];
__device__ float d_aggx[NMAX * DIN];
__device__ float d_h1[(size_t)NMAX * HID1];   // 164 MB
__device__ float d_y [(size_t)NMAX * HID2];   // 82 MB
__device__ float d_x2[(size_t)NMAX * HID2];   // 82 MB
__device__ float d_pooled[GMAX * HID2];
__device__ float d_hh1[GMAX * 1024];
__device__ float d_hh2[GMAX * 512];

// ---------------- CSR build ----------------
__global__ void k_zero_cnt(int n) {
    int i = blockIdx.x * blockDim.x + threadIdx.x;
    if (i < n) d_cnt[i] = 0;
}

__global__ void k_count(const int* __restrict__ dst, int E) {
    int e = blockIdx.x * blockDim.x + threadIdx.x;
    if (e < E) atomicAdd(&d_cnt[dst[e]], 1);
}

// single-block exclusive scan over cnt -> off, cur; also dinv = rsqrt(cnt+1)
__global__ void k_scan(int n) {
    __shared__ int sh[1024];
    __shared__ int carry;
    if (threadIdx.x == 0) carry = 0;
    __syncthreads();
    for (int base = 0; base < n; base += 1024) {
        int i = base + threadIdx.x;
        int v = (i < n) ? d_cnt[i] : 0;
        sh[threadIdx.x] = v;
        __syncthreads();
        for (int s = 1; s < 1024; s <<= 1) {
            int t = (threadIdx.x >= s) ? sh[threadIdx.x - s] : 0;
            __syncthreads();
            sh[threadIdx.x] += t;
            __syncthreads();
        }
        int inc = sh[threadIdx.x];
        if (i < n) {
            int o = carry + inc - v;
            d_off[i] = o;
            d_cur[i] = o;
            d_dinv[i] = rsqrtf((float)(v + 1));  // +1 for self loop
        }
        __syncthreads();
        if (threadIdx.x == 1023) carry += sh[1023];
        __syncthreads();
    }
    if (threadIdx.x == 0) d_off[n] = carry;
}

__global__ void k_scatter(const int* __restrict__ src, const int* __restrict__ dst, int E) {
    int e = blockIdx.x * blockDim.x + threadIdx.x;
    if (e < E) {
        int d = dst[e];
        int p = atomicAdd(&d_cur[d], 1);
        d_ssrc[p] = src[e];
    }
}

// ---------------- layer-1 aggregation in 36-dim space (warp per node) -------
__global__ void k_agg1(const int* __restrict__ ids, const float* __restrict__ feats,
                       const float* __restrict__ emb, int n) {
    int w = (blockIdx.x * blockDim.x + threadIdx.x) >> 5;
    int lane = threadIdx.x & 31;
    if (w >= n) return;
    int i = w;
    float di = d_dinv[i];
    // self loop contribution: norm = dinv_i^2, applied as di * (di * x_i)
    float a0 = di * emb[(size_t)ids[i] * 32 + lane];
    float a1 = (lane < 4) ? di * feats[(size_t)i * 4 + lane] : 0.f;
    int e0 = d_off[i], e1 = d_off[i + 1];
    for (int e = e0; e < e1; ++e) {
        int s = d_ssrc[e];
        float c = d_dinv[s];
        a0 += c * emb[(size_t)ids[s] * 32 + lane];
        if (lane < 4) a1 += c * feats[(size_t)s * 4 + lane];
    }
    d_aggx[(size_t)i * DIN + lane] = di * a0;
    if (lane < 4) d_aggx[(size_t)i * DIN + 32 + lane] = di * a1;
}

// ---------------- GEMM1: h1 = relu(aggx[M,36] @ W1[36,2048] + b1) -----------
// BM=128, BN=64, K=36 one-shot, 256 threads, 8x4 microtile
__global__ void k_gemm1(const float* __restrict__ W, const float* __restrict__ bias,
                        int M) {
    __shared__ float As[DIN][132];  // transposed A tile, padded
    __shared__ float Bs[DIN][64];
    int bm = blockIdx.x * 128;
    int bn = blockIdx.y * 64;
    int tid = threadIdx.x;
    int tx = tid & 15, ty = tid >> 4;

    // load A tile (128 x 36), 18 scalars/thread
#pragma unroll
    for (int t = 0; t < 18; ++t) {
        int idx = tid + t * 256;
        int r = idx / DIN;
        int c = idx - r * DIN;
        int g = bm + r;
        As[c][r] = (g < M) ? d_aggx[(size_t)g * DIN + c] : 0.f;
    }
    // load B tile (36 x 64), 9 scalars/thread
#pragma unroll
    for (int t = 0; t < 9; ++t) {
        int idx = tid + t * 256;
        int r = idx >> 6;
        int c = idx & 63;
        Bs[r][c] = W[(size_t)r * HID1 + bn + c];
    }
    __syncthreads();

    float acc[8][4];
#pragma unroll
    for (int i = 0; i < 8; ++i)
#pragma unroll
        for (int j = 0; j < 4; ++j) acc[i][j] = 0.f;

#pragma unroll
    for (int k = 0; k < DIN; ++k) {
        float a[8], b[4];
        *(float4*)(a)     = *(float4*)&As[k][ty * 8];
        *(float4*)(a + 4) = *(float4*)&As[k][ty * 8 + 4];
        *(float4*)(b)     = *(float4*)&Bs[k][tx * 4];
#pragma unroll
        for (int i = 0; i < 8; ++i)
#pragma unroll
            for (int j = 0; j < 4; ++j) acc[i][j] += a[i] * b[j];
    }

#pragma unroll
    for (int i = 0; i < 8; ++i) {
        int grow = bm + ty * 8 + i;
        if (grow >= M) continue;
#pragma unroll
        for (int j = 0; j < 4; ++j) {
            int gcol = bn + tx * 4 + j;
            float v = acc[i][j] + bias[gcol];
            d_h1[(size_t)grow * HID1 + gcol] = fmaxf(v, 0.f);
        }
    }
}

// ---------------- GEMM2: y = h1[M,2048] @ W2[2048,1024] ---------------------
// BM=BN=128, BK=16, 256 threads, 8x8 microtile
__global__ void k_gemm2(const float* __restrict__ B, int M) {
    const int K = HID1, N = HID2;
    __shared__ float As[16][132];
    __shared__ float Bs[16][128];
    int bm = blockIdx.x * 128;
    int bn = blockIdx.y * 128;
    int tid = threadIdx.x;
    int tx = tid & 15, ty = tid >> 4;

    float acc[8][8];
#pragma unroll
    for (int i = 0; i < 8; ++i)
#pragma unroll
        for (int j = 0; j < 8; ++j) acc[i][j] = 0.f;

    for (int kt = 0; kt < K; kt += 16) {
#pragma unroll
        for (int q = 0; q < 2; ++q) {
            int idx = tid + q * 256;
            int ar = idx >> 2;           // 0..127
            int ac = (idx & 3) * 4;      // 0,4,8,12
            int grow = bm + ar;
            float4 v = make_float4(0.f, 0.f, 0.f, 0.f);
            if (grow < M) v = *(const float4*)(d_h1 + (size_t)grow * K + kt + ac);
            As[ac + 0][ar] = v.x;
            As[ac + 1][ar] = v.y;
            As[ac + 2][ar] = v.z;
            As[ac + 3][ar] = v.w;
        }
#pragma unroll
        for (int q = 0; q < 2; ++q) {
            int idx = tid + q * 256;
            int br = idx >> 5;           // 0..15
            int bc = (idx & 31) * 4;     // 0..124
            *(float4*)&Bs[br][bc] = *(const float4*)(B + (size_t)(kt + br) * N + bn + bc);
        }
        __syncthreads();
#pragma unroll
        for (int k = 0; k < 16; ++k) {
            float a[8], b[8];
            *(float4*)(a)     = *(float4*)&As[k][ty * 8];
            *(float4*)(a + 4) = *(float4*)&As[k][ty * 8 + 4];
            *(float4*)(b)     = *(float4*)&Bs[k][tx * 8];
            *(float4*)(b + 4) = *(float4*)&Bs[k][tx * 8 + 4];
#pragma unroll
            for (int i = 0; i < 8; ++i)
#pragma unroll
                for (int j = 0; j < 8; ++j) acc[i][j] += a[i] * b[j];
        }
        __syncthreads();
    }

#pragma unroll
    for (int i = 0; i < 8; ++i) {
        int grow = bm + ty * 8 + i;
        if (grow >= M) continue;
#pragma unroll
        for (int j = 0; j < 8; j += 4) {
            float4 v = make_float4(acc[i][j], acc[i][j + 1], acc[i][j + 2], acc[i][j + 3]);
            *(float4*)(d_y + (size_t)grow * N + bn + tx * 8 + j) = v;
        }
    }
}

// ---------------- layer-2 aggregation + bias + relu (block per node) --------
__global__ void k_agg2(const float* __restrict__ b2, int n) {
    int i = blockIdx.x;
    int tid = threadIdx.x;            // 256 threads, float4 each = 1024 dims
    float di = d_dinv[i];
    const float4* Y = (const float4*)d_y;
    float4 v = Y[(size_t)i * 256 + tid];
    float c0 = di * di;
    float4 acc = make_float4(v.x * c0, v.y * c0, v.z * c0, v.w * c0);
    int e0 = d_off[i], e1 = d_off[i + 1];
    for (int e = e0; e < e1; ++e) {
        int s = d_ssrc[e];
        float c = di * d_dinv[s];
        float4 u = Y[(size_t)s * 256 + tid];
        acc.x += c * u.x;
        acc.y += c * u.y;
        acc.z += c * u.z;
        acc.w += c * u.w;
    }
    float4 bb = ((const float4*)b2)[tid];
    acc.x = fmaxf(acc.x + bb.x, 0.f);
    acc.y = fmaxf(acc.y + bb.y, 0.f);
    acc.z = fmaxf(acc.z + bb.z, 0.f);
    acc.w = fmaxf(acc.w + bb.w, 0.f);
    ((float4*)d_x2)[(size_t)i * 256 + tid] = acc;
}

// ---------------- mean pool per graph (batch sorted) -------------------------
__global__ void k_pool(const int* __restrict__ batch, int n) {
    int g = blockIdx.x;
    int tid = threadIdx.x;
    int lo = 0, hi = n;
    while (lo < hi) { int m = (lo + hi) >> 1; if (batch[m] < g) lo = m + 1; else hi = m; }
    int s0 = lo;
    hi = n;
    while (lo < hi) { int m = (lo + hi) >> 1; if (batch[m] <= g) lo = m + 1; else hi = m; }
    int s1 = lo;
    float4 acc = make_float4(0.f, 0.f, 0.f, 0.f);
    const float4* X = (const float4*)d_x2;
    for (int i = s0; i < s1; ++i) {
        float4 u = X[(size_t)i * 256 + tid];
        acc.x += u.x; acc.y += u.y; acc.z += u.z; acc.w += u.w;
    }
    int c = s1 - s0;
    float inv = 1.f / (float)(c > 0 ? c : 1);
    float4 r = make_float4(acc.x * inv, acc.y * inv, acc.z * inv, acc.w * inv);
    ((float4*)d_pooled)[g * 256 + tid] = r;
}

// ---------------- small MLP layers (block per graph row) --------------------
// These reference the __device__ scratch buffers DIRECTLY (device symbols are
// not valid as host-side kernel arguments -- that was the round-1 bug).
__global__ void k_mlp1(const float* __restrict__ W, const float* __restrict__ bias) {
    __shared__ float sp[1024];
    const int Kd = 1024, Nd = 1024;
    int g = blockIdx.x, tid = threadIdx.x;
    for (int k = tid; k < Kd; k += 256) sp[k] = d_pooled[(size_t)g * Kd + k];
    __syncthreads();
    float acc[4];
#pragma unroll
    for (int s = 0; s < 4; ++s) acc[s] = bias[tid + s * 256];
    for (int k = 0; k < Kd; ++k) {
        float pk = sp[k];
#pragma unroll
        for (int s = 0; s < 4; ++s)
            acc[s] += pk * W[(size_t)k * Nd + tid + s * 256];
    }
#pragma unroll
    for (int s = 0; s < 4; ++s)
        d_hh1[(size_t)g * Nd + tid + s * 256] = fmaxf(acc[s], 0.f);
}

__global__ void k_mlp2(const float* __restrict__ W, const float* __restrict__ bias) {
    __shared__ float sp[1024];
    const int Kd = 1024, Nd = 512;
    int g = blockIdx.x, tid = threadIdx.x;
    for (int k = tid; k < Kd; k += 256) sp[k] = d_hh1[(size_t)g * Kd + k];
    __syncthreads();
    float acc[2];
#pragma unroll
    for (int s = 0; s < 2; ++s) acc[s] = bias[tid + s * 256];
    for (int k = 0; k < Kd; ++k) {
        float pk = sp[k];
#pragma unroll
        for (int s = 0; s < 2; ++s)
            acc[s] += pk * W[(size_t)k * Nd + tid + s * 256];
    }
#pragma unroll
    for (int s = 0; s < 2; ++s)
        d_hh2[(size_t)g * Nd + tid + s * 256] = fmaxf(acc[s], 0.f);
}

__global__ void k_out(const float* __restrict__ oW, const float* __restrict__ ob,
                      float* __restrict__ out, int G) {
    int t = blockIdx.x * blockDim.x + threadIdx.x;
    if (t >= G * 2) return;
    int g = t >> 1, c = t & 1;
    float acc = ob[c];
    for (int k = 0; k < 512; ++k)
        acc += d_hh2[g * 512 + k] * oW[k * 2 + c];
    out[t] = acc;
}

// ---------------- launch --------------------------------------------------
extern "C" void kernel_launch(void* const* d_in, const int* in_sizes, int n_in,
                              void* d_out, int out_size) {
    const int*   ids   = (const int*)  d_in[0];
    const float* feats = (const float*)d_in[1];
    const int*   eidx  = (const int*)  d_in[2];
    const int*   batch = (const int*)  d_in[3];
    const float* emb   = (const float*)d_in[4];
    const float* W1    = (const float*)d_in[5];
    const float* b1    = (const float*)d_in[6];
    const float* W2    = (const float*)d_in[7];
    const float* b2    = (const float*)d_in[8];
    const float* hW1   = (const float*)d_in[9];
    const float* hb1   = (const float*)d_in[10];
    const float* hW2   = (const float*)d_in[11];
    const float* hb2   = (const float*)d_in[12];
    const float* oW    = (const float*)d_in[13];
    const float* ob    = (const float*)d_in[14];

    int n = in_sizes[0];
    int E = in_sizes[2] / 2;
    int G = out_size / 2;

    const int* src = eidx;
    const int* dst = eidx + E;

    k_zero_cnt<<<(n + 255) / 256, 256>>>(n);
    k_count<<<(E + 255) / 256, 256>>>(dst, E);
    k_scan<<<1, 1024>>>(n);
    k_scatter<<<(E + 255) / 256, 256>>>(src, dst, E);

    k_agg1<<<(n + 7) / 8, 256>>>(ids, feats, emb, n);

    dim3 g1((n + 127) / 128, HID1 / 64);
    k_gemm1<<<g1, 256>>>(W1, b1, n);

    dim3 g2((n + 127) / 128, HID2 / 128);
    k_gemm2<<<g2, 256>>>(W2, n);

    k_agg2<<<n, 256>>>(b2, n);

    k_pool<<<G, 256>>>(batch, n);

    k_mlp1<<<G, 256>>>(hW1, hb1);
    k_mlp2<<<G, 256>>>(hW2, hb2);

    k_out<<<1, 128>>>(oW, ob, (float*)d_out, G);
}

// round 4
// speedup vs baseline: 1.7747x; 1.7747x over previous
#include <cuda_runtime.h>
#include <cuda_bf16.h>
#include <stdint.h>

// Problem constants
#define NMAX 20000
#define EMAX 160000
#define GMAX 64
#define DIN  36      // 32 emb + 4 feats
#define HID1 2048
#define HID2 1024

// ---------------- scratch (device globals, no runtime alloc) ----------------
__device__ float d_dinv[NMAX];
__device__ int   d_cnt[NMAX];
__device__ int   d_off[NMAX + 1];
__device__ int   d_cur[NMAX];
__device__ int   d_ssrc[EMAX];
__device__ float d_aggx[NMAX * DIN];
__device__ __nv_bfloat16 d_h1hi[(size_t)NMAX * HID1];   // 82 MB
__device__ __nv_bfloat16 d_h1lo[(size_t)NMAX * HID1];   // 82 MB
__device__ __nv_bfloat16 d_w2thi[(size_t)HID2 * HID1];  // 4 MB, [N][K]
__device__ __nv_bfloat16 d_w2tlo[(size_t)HID2 * HID1];  // 4 MB
__device__ float d_y [(size_t)NMAX * HID2];   // 82 MB
__device__ float d_x2[(size_t)NMAX * HID2];   // 82 MB
__device__ float d_pooled[GMAX * HID2];
__device__ float d_hh1[GMAX * 1024];
__device__ float d_hh2[GMAX * 512];

// ---------------- PTX helpers (base ISA: sm_80+, valid on sm_103) -----------
__device__ __forceinline__ uint32_t smem_to_u32(const void* p) {
    uint32_t a;
    asm("{ .reg .u64 t; cvta.to.shared.u64 t, %1; cvt.u32.u64 %0, t; }" : "=r"(a) : "l"(p));
    return a;
}

#define CP_ASYNC16(dst, src, sz) \
    asm volatile("cp.async.cg.shared.global [%0], [%1], 16, %2;" \
        :: "r"(dst), "l"(src), "r"(sz) : "memory")
#define CP_COMMIT()  asm volatile("cp.async.commit_group;" ::: "memory")
#define CP_WAIT0()   asm volatile("cp.async.wait_group 0;" ::: "memory")

#define LDM_X4(r0, r1, r2, r3, addr) \
    asm volatile("ldmatrix.sync.aligned.m8n8.x4.shared.b16 {%0,%1,%2,%3}, [%4];" \
        : "=r"(r0), "=r"(r1), "=r"(r2), "=r"(r3) : "r"(addr))

#define MMA_BF16(c, a, b0v, b1v) \
    asm volatile("mma.sync.aligned.m16n8k16.row.col.f32.bf16.bf16.f32 " \
        "{%0,%1,%2,%3},{%4,%5,%6,%7},{%8,%9},{%0,%1,%2,%3};" \
        : "+f"((c)[0]), "+f"((c)[1]), "+f"((c)[2]), "+f"((c)[3]) \
        : "r"((a)[0]), "r"((a)[1]), "r"((a)[2]), "r"((a)[3]), "r"(b0v), "r"(b1v))

// ---------------- CSR build ----------------
__global__ void k_zero_cnt(int n) {
    int i = blockIdx.x * blockDim.x + threadIdx.x;
    if (i < n) d_cnt[i] = 0;
}

__global__ void k_count(const int* __restrict__ dst, int E) {
    int e = blockIdx.x * blockDim.x + threadIdx.x;
    if (e < E) atomicAdd(&d_cnt[dst[e]], 1);
}

__global__ void k_scan(int n) {
    __shared__ int sh[1024];
    __shared__ int carry;
    if (threadIdx.x == 0) carry = 0;
    __syncthreads();
    for (int base = 0; base < n; base += 1024) {
        int i = base + threadIdx.x;
        int v = (i < n) ? d_cnt[i] : 0;
        sh[threadIdx.x] = v;
        __syncthreads();
        for (int s = 1; s < 1024; s <<= 1) {
            int t = (threadIdx.x >= s) ? sh[threadIdx.x - s] : 0;
            __syncthreads();
            sh[threadIdx.x] += t;
            __syncthreads();
        }
        int inc = sh[threadIdx.x];
        if (i < n) {
            int o = carry + inc - v;
            d_off[i] = o;
            d_cur[i] = o;
            d_dinv[i] = rsqrtf((float)(v + 1));
        }
        __syncthreads();
        if (threadIdx.x == 1023) carry += sh[1023];
        __syncthreads();
    }
    if (threadIdx.x == 0) d_off[n] = carry;
}

__global__ void k_scatter(const int* __restrict__ src, const int* __restrict__ dst, int E) {
    int e = blockIdx.x * blockDim.x + threadIdx.x;
    if (e < E) {
        int d = dst[e];
        int p = atomicAdd(&d_cur[d], 1);
        d_ssrc[p] = src[e];
    }
}

// ---------------- layer-1 aggregation in 36-dim space ------------------------
__global__ void k_agg1(const int* __restrict__ ids, const float* __restrict__ feats,
                       const float* __restrict__ emb, int n) {
    int w = (blockIdx.x * blockDim.x + threadIdx.x) >> 5;
    int lane = threadIdx.x & 31;
    if (w >= n) return;
    int i = w;
    float di = d_dinv[i];
    float a0 = di * emb[(size_t)ids[i] * 32 + lane];
    float a1 = (lane < 4) ? di * feats[(size_t)i * 4 + lane] : 0.f;
    int e0 = d_off[i], e1 = d_off[i + 1];
    for (int e = e0; e < e1; ++e) {
        int s = d_ssrc[e];
        float c = d_dinv[s];
        a0 += c * emb[(size_t)ids[s] * 32 + lane];
        if (lane < 4) a1 += c * feats[(size_t)s * 4 + lane];
    }
    d_aggx[(size_t)i * DIN + lane] = di * a0;
    if (lane < 4) d_aggx[(size_t)i * DIN + 32 + lane] = di * a1;
}

// ---------------- GEMM1: h1 = relu(aggx @ W1 + b1) -> bf16 hi/lo -----------
__global__ void k_gemm1(const float* __restrict__ W, const float* __restrict__ bias,
                        int M) {
    __shared__ float As[DIN][132];
    __shared__ float Bs[DIN][64];
    int bm = blockIdx.x * 128;
    int bn = blockIdx.y * 64;
    int tid = threadIdx.x;
    int tx = tid & 15, ty = tid >> 4;

#pragma unroll
    for (int t = 0; t < 18; ++t) {
        int idx = tid + t * 256;
        int r = idx / DIN;
        int c = idx - r * DIN;
        int g = bm + r;
        As[c][r] = (g < M) ? d_aggx[(size_t)g * DIN + c] : 0.f;
    }
#pragma unroll
    for (int t = 0; t < 9; ++t) {
        int idx = tid + t * 256;
        int r = idx >> 6;
        int c = idx & 63;
        Bs[r][c] = W[(size_t)r * HID1 + bn + c];
    }
    __syncthreads();

    float acc[8][4];
#pragma unroll
    for (int i = 0; i < 8; ++i)
#pragma unroll
        for (int j = 0; j < 4; ++j) acc[i][j] = 0.f;

#pragma unroll
    for (int k = 0; k < DIN; ++k) {
        float a[8], b[4];
        *(float4*)(a)     = *(float4*)&As[k][ty * 8];
        *(float4*)(a + 4) = *(float4*)&As[k][ty * 8 + 4];
        *(float4*)(b)     = *(float4*)&Bs[k][tx * 4];
#pragma unroll
        for (int i = 0; i < 8; ++i)
#pragma unroll
            for (int j = 0; j < 4; ++j) acc[i][j] += a[i] * b[j];
    }

#pragma unroll
    for (int i = 0; i < 8; ++i) {
        int grow = bm + ty * 8 + i;
        if (grow >= M) continue;
#pragma unroll
        for (int j = 0; j < 4; ++j) {
            int gcol = bn + tx * 4 + j;
            float v = fmaxf(acc[i][j] + bias[gcol], 0.f);
            __nv_bfloat16 h = __float2bfloat16(v);
            float lo = v - __bfloat162float(h);
            d_h1hi[(size_t)grow * HID1 + gcol] = h;
            d_h1lo[(size_t)grow * HID1 + gcol] = __float2bfloat16(lo);
        }
    }
}

// ---------------- prep B: W2 [K,N] fp32 -> W2^T [N,K] bf16 hi/lo ------------
__global__ void k_prepB(const float* __restrict__ W2) {
    __shared__ float t[32][33];
    int nt = blockIdx.x * 32, kt = blockIdx.y * 32;
    int x = threadIdx.x, y = threadIdx.y;
#pragma unroll
    for (int j = 0; j < 4; ++j)
        t[y + j * 8][x] = W2[(size_t)(kt + y + j * 8) * HID2 + nt + x];
    __syncthreads();
#pragma unroll
    for (int j = 0; j < 4; ++j) {
        float v = t[x][y + j * 8];
        __nv_bfloat16 h = __float2bfloat16(v);
        float lo = v - __bfloat162float(h);
        size_t o = (size_t)(nt + y + j * 8) * HID1 + kt + x;
        d_w2thi[o] = h;
        d_w2tlo[o] = __float2bfloat16(lo);
    }
}

// ---------------- GEMM2 via mma.sync bf16 3-pass split: y = h1 @ W2 ---------
// Tile 128(M) x 128(N) x 32(K chunk). 8 warps = 2(m) x 4(n), warp tile 64x32.
// SMEM per buffer: Ah[128][40] | Al | Bh[128][40] | Bl  (rows padded to 80B ->
// ldmatrix 8-row fetches are bank-conflict-free). Double buffered w/ cp.async.
#define G2_ROWB   80                       // bytes per padded row (40 bf16)
#define G2_MAT    (128 * G2_ROWB)          // 10240 B
#define G2_BUF    (4 * G2_MAT)             // 40960 B
#define G2_SMEM   (2 * G2_BUF)             // 81920 B
#define G2_AH     0
#define G2_AL     G2_MAT
#define G2_BH     (2 * G2_MAT)
#define G2_BL     (3 * G2_MAT)

__global__ void __launch_bounds__(256, 1) k_gemm2_mma(int M) {
    extern __shared__ char smem[];
    uint32_t sb = smem_to_u32(smem);
    const int tid = threadIdx.x;
    const int lane = tid & 31, wid = tid >> 5;
    const int wm = wid >> 2, wn = wid & 3;          // 2 x 4 warp grid
    const int bn = blockIdx.x * 128;                 // N fast -> A tile shared
    const int bm = blockIdx.y * 128;                 // across consecutive CTAs

    const int NCHUNK = HID1 / 32;   // 64

    // ---- fill one buffer with chunk kt via cp.async (zfill OOB A rows) ----
    auto fill = [&](int buf, int kt) {
        uint32_t base = sb + buf * G2_BUF;
#pragma unroll
        for (int i = 0; i < 2; ++i) {
            int idx = tid + i * 256;        // 0..511
            int row = idx >> 2;             // 0..127
            int u = idx & 3;                // 0..3  (16B units of 32-bf16 row)
            uint32_t so = (uint32_t)(row * G2_ROWB + u * 16);
            // A
            int gr = bm + row;
            int szA = (gr < M) ? 16 : 0;
            size_t goA = (size_t)gr * HID1 + kt + u * 8;
            CP_ASYNC16(base + G2_AH + so, (const char*)(d_h1hi + goA), szA);
            CP_ASYNC16(base + G2_AL + so, (const char*)(d_h1lo + goA), szA);
            // B (always in bounds)
            size_t goB = (size_t)(bn + row) * HID1 + kt + u * 8;
            CP_ASYNC16(base + G2_BH + so, (const char*)(d_w2thi + goB), 16);
            CP_ASYNC16(base + G2_BL + so, (const char*)(d_w2tlo + goB), 16);
        }
    };

    float acc[4][4][4];
#pragma unroll
    for (int i = 0; i < 4; ++i)
#pragma unroll
        for (int j = 0; j < 4; ++j)
#pragma unroll
            for (int q = 0; q < 4; ++q) acc[i][j][q] = 0.f;

    fill(0, 0);
    CP_COMMIT();
    CP_WAIT0();
    __syncthreads();

    const int lr = lane & 7;         // ldmatrix row within 8
    const int lm = lane >> 3;        // ldmatrix matrix index 0..3

    for (int c = 0; c < NCHUNK; ++c) {
        if (c + 1 < NCHUNK) {
            fill((c + 1) & 1, (c + 1) * 32);
            CP_COMMIT();
        }
        uint32_t base = sb + (c & 1) * G2_BUF;

        // B fragments for the whole chunk: matrix lm covers k-block lm*8
        uint32_t bh[4][4], bl[4][4];
#pragma unroll
        for (int nt = 0; nt < 4; ++nt) {
            uint32_t baddr = base + G2_BH +
                (uint32_t)((wn * 32 + nt * 8 + lr) * G2_ROWB + lm * 16);
            LDM_X4(bh[nt][0], bh[nt][1], bh[nt][2], bh[nt][3], baddr);
            LDM_X4(bl[nt][0], bl[nt][1], bl[nt][2], bl[nt][3], baddr + (G2_BL - G2_BH));
        }

#pragma unroll
        for (int ks = 0; ks < 2; ++ks) {
            uint32_t ah[4][4], al[4][4];
#pragma unroll
            for (int mt = 0; mt < 4; ++mt) {
                uint32_t aaddr = base + G2_AH +
                    (uint32_t)((wm * 64 + mt * 16 + (lm & 1) * 8 + lr) * G2_ROWB +
                               ks * 32 + (lm >> 1) * 16);
                LDM_X4(ah[mt][0], ah[mt][1], ah[mt][2], ah[mt][3], aaddr);
                LDM_X4(al[mt][0], al[mt][1], al[mt][2], al[mt][3], aaddr + G2_MAT);
            }
#pragma unroll
            for (int mt = 0; mt < 4; ++mt)
#pragma unroll
                for (int nt = 0; nt < 4; ++nt) {
                    MMA_BF16(acc[mt][nt], ah[mt], bh[nt][2 * ks], bh[nt][2 * ks + 1]);
                    MMA_BF16(acc[mt][nt], ah[mt], bl[nt][2 * ks], bl[nt][2 * ks + 1]);
                    MMA_BF16(acc[mt][nt], al[mt], bh[nt][2 * ks], bh[nt][2 * ks + 1]);
                }
        }
        CP_WAIT0();
        __syncthreads();
    }

    // ---- epilogue: acc -> d_y ----
    int r0 = lane >> 2;
    int c0 = (lane & 3) * 2;
#pragma unroll
    for (int mt = 0; mt < 4; ++mt) {
#pragma unroll
        for (int nt = 0; nt < 4; ++nt) {
            int grow = bm + wm * 64 + mt * 16 + r0;
            int gcol = bn + wn * 32 + nt * 8 + c0;
            if (grow < M)
                *(float2*)(d_y + (size_t)grow * HID2 + gcol) =
                    make_float2(acc[mt][nt][0], acc[mt][nt][1]);
            if (grow + 8 < M)
                *(float2*)(d_y + (size_t)(grow + 8) * HID2 + gcol) =
                    make_float2(acc[mt][nt][2], acc[mt][nt][3]);
        }
    }
}

// ---------------- layer-2 aggregation + bias + relu --------------------------
__global__ void k_agg2(const float* __restrict__ b2, int n) {
    int i = blockIdx.x;
    int tid = threadIdx.x;
    float di = d_dinv[i];
    const float4* Y = (const float4*)d_y;
    float4 v = Y[(size_t)i * 256 + tid];
    float c0 = di * di;
    float4 acc = make_float4(v.x * c0, v.y * c0, v.z * c0, v.w * c0);
    int e0 = d_off[i], e1 = d_off[i + 1];
    for (int e = e0; e < e1; ++e) {
        int s = d_ssrc[e];
        float c = di * d_dinv[s];
        float4 u = Y[(size_t)s * 256 + tid];
        acc.x += c * u.x;
        acc.y += c * u.y;
        acc.z += c * u.z;
        acc.w += c * u.w;
    }
    float4 bb = ((const float4*)b2)[tid];
    acc.x = fmaxf(acc.x + bb.x, 0.f);
    acc.y = fmaxf(acc.y + bb.y, 0.f);
    acc.z = fmaxf(acc.z + bb.z, 0.f);
    acc.w = fmaxf(acc.w + bb.w, 0.f);
    ((float4*)d_x2)[(size_t)i * 256 + tid] = acc;
}

// ---------------- mean pool per graph (batch sorted) --------------------------
__global__ void k_pool(const int* __restrict__ batch, int n) {
    int g = blockIdx.x;
    int tid = threadIdx.x;
    int lo = 0, hi = n;
    while (lo < hi) { int m = (lo + hi) >> 1; if (batch[m] < g) lo = m + 1; else hi = m; }
    int s0 = lo;
    hi = n;
    while (lo < hi) { int m = (lo + hi) >> 1; if (batch[m] <= g) lo = m + 1; else hi = m; }
    int s1 = lo;
    float4 acc = make_float4(0.f, 0.f, 0.f, 0.f);
    const float4* X = (const float4*)d_x2;
    for (int i = s0; i < s1; ++i) {
        float4 u = X[(size_t)i * 256 + tid];
        acc.x += u.x; acc.y += u.y; acc.z += u.z; acc.w += u.w;
    }
    int c = s1 - s0;
    float inv = 1.f / (float)(c > 0 ? c : 1);
    ((float4*)d_pooled)[g * 256 + tid] =
        make_float4(acc.x * inv, acc.y * inv, acc.z * inv, acc.w * inv);
}

// ---------------- small MLP head ---------------------------------------------
__global__ void k_mlp1(const float* __restrict__ W, const float* __restrict__ bias) {
    __shared__ float sp[1024];
    const int Kd = 1024, Nd = 1024;
    int g = blockIdx.x, tid = threadIdx.x;
    for (int k = tid; k < Kd; k += 256) sp[k] = d_pooled[(size_t)g * Kd + k];
    __syncthreads();
    float acc[4];
#pragma unroll
    for (int s = 0; s < 4; ++s) acc[s] = bias[tid + s * 256];
    for (int k = 0; k < Kd; ++k) {
        float pk = sp[k];
#pragma unroll
        for (int s = 0; s < 4; ++s)
            acc[s] += pk * W[(size_t)k * Nd + tid + s * 256];
    }
#pragma unroll
    for (int s = 0; s < 4; ++s)
        d_hh1[(size_t)g * Nd + tid + s * 256] = fmaxf(acc[s], 0.f);
}

__global__ void k_mlp2(const float* __restrict__ W, const float* __restrict__ bias) {
    __shared__ float sp[1024];
    const int Kd = 1024, Nd = 512;
    int g = blockIdx.x, tid = threadIdx.x;
    for (int k = tid; k < Kd; k += 256) sp[k] = d_hh1[(size_t)g * Kd + k];
    __syncthreads();
    float acc[2];
#pragma unroll
    for (int s = 0; s < 2; ++s) acc[s] = bias[tid + s * 256];
    for (int k = 0; k < Kd; ++k) {
        float pk = sp[k];
#pragma unroll
        for (int s = 0; s < 2; ++s)
            acc[s] += pk * W[(size_t)k * Nd + tid + s * 256];
    }
#pragma unroll
    for (int s = 0; s < 2; ++s)
        d_hh2[(size_t)g * Nd + tid + s * 256] = fmaxf(acc[s], 0.f);
}

__global__ void k_out(const float* __restrict__ oW, const float* __restrict__ ob,
                      float* __restrict__ out, int G) {
    int t = blockIdx.x * blockDim.x + threadIdx.x;
    if (t >= G * 2) return;
    int g = t >> 1, c = t & 1;
    float acc = ob[c];
    for (int k = 0; k < 512; ++k)
        acc += d_hh2[g * 512 + k] * oW[k * 2 + c];
    out[t] = acc;
}

// ---------------- launch ------------------------------------------------------
extern "C" void kernel_launch(void* const* d_in, const int* in_sizes, int n_in,
                              void* d_out, int out_size) {
    const int*   ids   = (const int*)  d_in[0];
    const float* feats = (const float*)d_in[1];
    const int*   eidx  = (const int*)  d_in[2];
    const int*   batch = (const int*)  d_in[3];
    const float* emb   = (const float*)d_in[4];
    const float* W1    = (const float*)d_in[5];
    const float* b1    = (const float*)d_in[6];
    const float* W2    = (const float*)d_in[7];
    const float* b2    = (const float*)d_in[8];
    const float* hW1   = (const float*)d_in[9];
    const float* hb1   = (const float*)d_in[10];
    const float* hW2   = (const float*)d_in[11];
    const float* hb2   = (const float*)d_in[12];
    const float* oW    = (const float*)d_in[13];
    const float* ob    = (const float*)d_in[14];

    int n = in_sizes[0];
    int E = in_sizes[2] / 2;
    int G = out_size / 2;

    const int* src = eidx;
    const int* dst = eidx + E;

    static bool attr_done = false;
    if (!attr_done) {
        cudaFuncSetAttribute(k_gemm2_mma, cudaFuncAttributeMaxDynamicSharedMemorySize,
                             G2_SMEM);
        attr_done = true;
    }

    k_zero_cnt<<<(n + 255) / 256, 256>>>(n);
    k_count<<<(E + 255) / 256, 256>>>(dst, E);
    k_scan<<<1, 1024>>>(n);
    k_scatter<<<(E + 255) / 256, 256>>>(src, dst, E);

    dim3 gp(HID2 / 32, HID1 / 32);
    k_prepB<<<gp, dim3(32, 8)>>>(W2);

    k_agg1<<<(n + 7) / 8, 256>>>(ids, feats, emb, n);

    dim3 g1((n + 127) / 128, HID1 / 64);
    k_gemm1<<<g1, 256>>>(W1, b1, n);

    dim3 g2(HID2 / 128, (n + 127) / 128);   // x = N-block (fast), y = M-block
    k_gemm2_mma<<<g2, 256, G2_SMEM>>>(n);

    k_agg2<<<n, 256>>>(b2, n);

    k_pool<<<G, 256>>>(batch, n);

    k_mlp1<<<G, 256>>>(hW1, hb1);
    k_mlp2<<<G, 256>>>(hW2, hb2);

    k_out<<<1, 128>>>(oW, ob, (float*)d_out, G);
}

// round 5
// speedup vs baseline: 3.0667x; 1.7280x over previous
#include <cuda_runtime.h>
#include <cuda_fp16.h>
#include <stdint.h>

// Problem constants
#define NMAX 20000
#define EMAX 160000
#define GMAX 64
#define DIN  36      // 32 emb + 4 feats
#define HID1 2048
#define HID2 1024

// ---------------- scratch (device globals, no runtime alloc) ----------------
__device__ float d_dinv[NMAX];
__device__ int   d_cnt[NMAX];
__device__ int   d_off[NMAX + 1];
__device__ int   d_cur[NMAX];
__device__ int   d_ssrc[EMAX];
__device__ float d_aggx[NMAX * DIN];
__device__ __half d_h1h[(size_t)NMAX * HID1];   // 41 MB (fp16 h1)
__device__ __half d_w2t[(size_t)HID2 * HID1];   // 4 MB, [N][K] fp16
__device__ float d_y [(size_t)NMAX * HID2];   // 82 MB
__device__ float d_x2[(size_t)NMAX * HID2];   // 82 MB
__device__ float d_pooled[GMAX * HID2];
__device__ float d_hh1[GMAX * 1024];
__device__ float d_hh2[GMAX * 512];

// ---------------- PTX helpers (base ISA: sm_80+, valid on sm_103) -----------
__device__ __forceinline__ uint32_t smem_to_u32(const void* p) {
    uint32_t a;
    asm("{ .reg .u64 t; cvta.to.shared.u64 t, %1; cvt.u32.u64 %0, t; }" : "=r"(a) : "l"(p));
    return a;
}

#define CP_ASYNC16(dst, src, sz) \
    asm volatile("cp.async.cg.shared.global [%0], [%1], 16, %2;" \
        :: "r"(dst), "l"(src), "r"(sz) : "memory")
#define CP_COMMIT()  asm volatile("cp.async.commit_group;" ::: "memory")
#define CP_WAIT0()   asm volatile("cp.async.wait_group 0;" ::: "memory")

#define LDM_X4(r0, r1, r2, r3, addr) \
    asm volatile("ldmatrix.sync.aligned.m8n8.x4.shared.b16 {%0,%1,%2,%3}, [%4];" \
        : "=r"(r0), "=r"(r1), "=r"(r2), "=r"(r3) : "r"(addr))

#define MMA_FP16(c, a, b0v, b1v) \
    asm volatile("mma.sync.aligned.m16n8k16.row.col.f32.f16.f16.f32 " \
        "{%0,%1,%2,%3},{%4,%5,%6,%7},{%8,%9},{%0,%1,%2,%3};" \
        : "+f"((c)[0]), "+f"((c)[1]), "+f"((c)[2]), "+f"((c)[3]) \
        : "r"((a)[0]), "r"((a)[1]), "r"((a)[2]), "r"((a)[3]), "r"(b0v), "r"(b1v))

// ---------------- CSR build ----------------
__global__ void k_zero_cnt(int n) {
    int i = blockIdx.x * blockDim.x + threadIdx.x;
    if (i < n) d_cnt[i] = 0;
}

__global__ void k_count(const int* __restrict__ dst, int E) {
    int e = blockIdx.x * blockDim.x + threadIdx.x;
    if (e < E) atomicAdd(&d_cnt[dst[e]], 1);
}

__global__ void k_scan(int n) {
    __shared__ int sh[1024];
    __shared__ int carry;
    if (threadIdx.x == 0) carry = 0;
    __syncthreads();
    for (int base = 0; base < n; base += 1024) {
        int i = base + threadIdx.x;
        int v = (i < n) ? d_cnt[i] : 0;
        sh[threadIdx.x] = v;
        __syncthreads();
        for (int s = 1; s < 1024; s <<= 1) {
            int t = (threadIdx.x >= s) ? sh[threadIdx.x - s] : 0;
            __syncthreads();
            sh[threadIdx.x] += t;
            __syncthreads();
        }
        int inc = sh[threadIdx.x];
        if (i < n) {
            int o = carry + inc - v;
            d_off[i] = o;
            d_cur[i] = o;
            d_dinv[i] = rsqrtf((float)(v + 1));
        }
        __syncthreads();
        if (threadIdx.x == 1023) carry += sh[1023];
        __syncthreads();
    }
    if (threadIdx.x == 0) d_off[n] = carry;
}

__global__ void k_scatter(const int* __restrict__ src, const int* __restrict__ dst, int E) {
    int e = blockIdx.x * blockDim.x + threadIdx.x;
    if (e < E) {
        int d = dst[e];
        int p = atomicAdd(&d_cur[d], 1);
        d_ssrc[p] = src[e];
    }
}

// ---------------- layer-1 aggregation in 36-dim space ------------------------
__global__ void k_agg1(const int* __restrict__ ids, const float* __restrict__ feats,
                       const float* __restrict__ emb, int n) {
    int w = (blockIdx.x * blockDim.x + threadIdx.x) >> 5;
    int lane = threadIdx.x & 31;
    if (w >= n) return;
    int i = w;
    float di = d_dinv[i];
    float a0 = di * emb[(size_t)ids[i] * 32 + lane];
    float a1 = (lane < 4) ? di * feats[(size_t)i * 4 + lane] : 0.f;
    int e0 = d_off[i], e1 = d_off[i + 1];
    for (int e = e0; e < e1; ++e) {
        int s = d_ssrc[e];
        float c = d_dinv[s];
        a0 += c * emb[(size_t)ids[s] * 32 + lane];
        if (lane < 4) a1 += c * feats[(size_t)s * 4 + lane];
    }
    d_aggx[(size_t)i * DIN + lane] = di * a0;
    if (lane < 4) d_aggx[(size_t)i * DIN + 32 + lane] = di * a1;
}

// ---------------- GEMM1: h1 = relu(aggx @ W1 + b1) -> fp16 ------------------
__global__ void k_gemm1(const float* __restrict__ W, const float* __restrict__ bias,
                        int M) {
    __shared__ float As[DIN][132];
    __shared__ float Bs[DIN][64];
    int bm = blockIdx.x * 128;
    int bn = blockIdx.y * 64;
    int tid = threadIdx.x;
    int tx = tid & 15, ty = tid >> 4;

#pragma unroll
    for (int t = 0; t < 18; ++t) {
        int idx = tid + t * 256;
        int r = idx / DIN;
        int c = idx - r * DIN;
        int g = bm + r;
        As[c][r] = (g < M) ? d_aggx[(size_t)g * DIN + c] : 0.f;
    }
#pragma unroll
    for (int t = 0; t < 9; ++t) {
        int idx = tid + t * 256;
        int r = idx >> 6;
        int c = idx & 63;
        Bs[r][c] = W[(size_t)r * HID1 + bn + c];
    }
    __syncthreads();

    float acc[8][4];
#pragma unroll
    for (int i = 0; i < 8; ++i)
#pragma unroll
        for (int j = 0; j < 4; ++j) acc[i][j] = 0.f;

#pragma unroll
    for (int k = 0; k < DIN; ++k) {
        float a[8], b[4];
        *(float4*)(a)     = *(float4*)&As[k][ty * 8];
        *(float4*)(a + 4) = *(float4*)&As[k][ty * 8 + 4];
        *(float4*)(b)     = *(float4*)&Bs[k][tx * 4];
#pragma unroll
        for (int i = 0; i < 8; ++i)
#pragma unroll
            for (int j = 0; j < 4; ++j) acc[i][j] += a[i] * b[j];
    }

#pragma unroll
    for (int i = 0; i < 8; ++i) {
        int grow = bm + ty * 8 + i;
        if (grow >= M) continue;
#pragma unroll
        for (int j = 0; j < 4; j += 2) {
            int gcol = bn + tx * 4 + j;
            float v0 = fmaxf(acc[i][j] + bias[gcol], 0.f);
            float v1 = fmaxf(acc[i][j + 1] + bias[gcol + 1], 0.f);
            *(__half2*)(d_h1h + (size_t)grow * HID1 + gcol) =
                __floats2half2_rn(v0, v1);
        }
    }
}

// ---------------- prep B: W2 [K,N] fp32 -> W2^T [N,K] fp16 ------------------
__global__ void k_prepB(const float* __restrict__ W2) {
    __shared__ float t[32][33];
    int nt = blockIdx.x * 32, kt = blockIdx.y * 32;
    int x = threadIdx.x, y = threadIdx.y;
#pragma unroll
    for (int j = 0; j < 4; ++j)
        t[y + j * 8][x] = W2[(size_t)(kt + y + j * 8) * HID2 + nt + x];
    __syncthreads();
#pragma unroll
    for (int j = 0; j < 4; ++j) {
        float v = t[x][y + j * 8];
        d_w2t[(size_t)(nt + y + j * 8) * HID1 + kt + x] = __float2half_rn(v);
    }
}

// ---------------- GEMM2 via mma.sync fp16 single pass: y = h1 @ W2 ----------
// Tile 128(M) x 128(N) x 32(K chunk). 8 warps = 2(m) x 4(n), warp tile 64x32.
// SMEM per buffer: A[128][40] | B[128][40] (fp16, rows padded to 80B ->
// ldmatrix 8-row fetches bank-conflict-free). Double buffered w/ cp.async.
#define G2_ROWB   80                       // bytes per padded row (40 fp16)
#define G2_MAT    (128 * G2_ROWB)          // 10240 B
#define G2_BUF    (2 * G2_MAT)             // 20480 B
#define G2_SMEM   (2 * G2_BUF)             // 40960 B

__global__ void __launch_bounds__(256, 2) k_gemm2_mma(int M) {
    extern __shared__ char smem[];
    uint32_t sb = smem_to_u32(smem);
    const int tid = threadIdx.x;
    const int lane = tid & 31, wid = tid >> 5;
    const int wm = wid >> 2, wn = wid & 3;          // 2 x 4 warp grid
    const int bn = blockIdx.x * 128;                 // N fast -> A tile shared
    const int bm = blockIdx.y * 128;                 // across consecutive CTAs

    const int NCHUNK = HID1 / 32;   // 64

    auto fill = [&](int buf, int kt) {
        uint32_t base = sb + buf * G2_BUF;
#pragma unroll
        for (int i = 0; i < 2; ++i) {
            int idx = tid + i * 256;        // 0..511
            int row = idx >> 2;             // 0..127
            int u = idx & 3;                // 16B unit within 64B row data
            uint32_t so = (uint32_t)(row * G2_ROWB + u * 16);
            int gr = bm + row;
            int szA = (gr < M) ? 16 : 0;
            CP_ASYNC16(base + so, (const char*)(d_h1h + (size_t)gr * HID1 + kt + u * 8), szA);
            CP_ASYNC16(base + G2_MAT + so,
                       (const char*)(d_w2t + (size_t)(bn + row) * HID1 + kt + u * 8), 16);
        }
    };

    float acc[4][4][4];
#pragma unroll
    for (int i = 0; i < 4; ++i)
#pragma unroll
        for (int j = 0; j < 4; ++j)
#pragma unroll
            for (int q = 0; q < 4; ++q) acc[i][j][q] = 0.f;

    fill(0, 0);
    CP_COMMIT();
    CP_WAIT0();
    __syncthreads();

    const int lr = lane & 7;         // ldmatrix row within 8
    const int lm = lane >> 3;        // ldmatrix matrix index 0..3

    for (int c = 0; c < NCHUNK; ++c) {
        if (c + 1 < NCHUNK) {
            fill((c + 1) & 1, (c + 1) * 32);
            CP_COMMIT();
        }
        uint32_t base = sb + (c & 1) * G2_BUF;

        // B fragments: per nt, x4 covers n8 x k32 (whole chunk)
        uint32_t bf[4][4];
#pragma unroll
        for (int nt = 0; nt < 4; ++nt) {
            uint32_t baddr = base + G2_MAT +
                (uint32_t)((wn * 32 + nt * 8 + lr) * G2_ROWB + lm * 16);
            LDM_X4(bf[nt][0], bf[nt][1], bf[nt][2], bf[nt][3], baddr);
        }

#pragma unroll
        for (int ks = 0; ks < 2; ++ks) {
            uint32_t af[4][4];
#pragma unroll
            for (int mt = 0; mt < 4; ++mt) {
                uint32_t aaddr = base +
                    (uint32_t)((wm * 64 + mt * 16 + (lm & 1) * 8 + lr) * G2_ROWB +
                               ks * 32 + (lm >> 1) * 16);
                LDM_X4(af[mt][0], af[mt][1], af[mt][2], af[mt][3], aaddr);
            }
#pragma unroll
            for (int mt = 0; mt < 4; ++mt)
#pragma unroll
                for (int nt = 0; nt < 4; ++nt)
                    MMA_FP16(acc[mt][nt], af[mt], bf[nt][2 * ks], bf[nt][2 * ks + 1]);
        }
        CP_WAIT0();
        __syncthreads();
    }

    // ---- epilogue: acc -> d_y ----
    int r0 = lane >> 2;
    int c0 = (lane & 3) * 2;
#pragma unroll
    for (int mt = 0; mt < 4; ++mt) {
#pragma unroll
        for (int nt = 0; nt < 4; ++nt) {
            int grow = bm + wm * 64 + mt * 16 + r0;
            int gcol = bn + wn * 32 + nt * 8 + c0;
            if (grow < M)
                *(float2*)(d_y + (size_t)grow * HID2 + gcol) =
                    make_float2(acc[mt][nt][0], acc[mt][nt][1]);
            if (grow + 8 < M)
                *(float2*)(d_y + (size_t)(grow + 8) * HID2 + gcol) =
                    make_float2(acc[mt][nt][2], acc[mt][nt][3]);
        }
    }
}

// ---------------- layer-2 aggregation + bias + relu --------------------------
__global__ void k_agg2(const float* __restrict__ b2, int n) {
    int i = blockIdx.x;
    int tid = threadIdx.x;
    float di = d_dinv[i];
    const float4* Y = (const float4*)d_y;
    float4 v = Y[(size_t)i * 256 + tid];
    float c0 = di * di;
    float4 acc = make_float4(v.x * c0, v.y * c0, v.z * c0, v.w * c0);
    int e0 = d_off[i], e1 = d_off[i + 1];
    for (int e = e0; e < e1; ++e) {
        int s = d_ssrc[e];
        float c = di * d_dinv[s];
        float4 u = Y[(size_t)s * 256 + tid];
        acc.x += c * u.x;
        acc.y += c * u.y;
        acc.z += c * u.z;
        acc.w += c * u.w;
    }
    float4 bb = ((const float4*)b2)[tid];
    acc.x = fmaxf(acc.x + bb.x, 0.f);
    acc.y = fmaxf(acc.y + bb.y, 0.f);
    acc.z = fmaxf(acc.z + bb.z, 0.f);
    acc.w = fmaxf(acc.w + bb.w, 0.f);
    ((float4*)d_x2)[(size_t)i * 256 + tid] = acc;
}

// ---------------- mean pool per graph (batch sorted) --------------------------
__global__ void k_pool(const int* __restrict__ batch, int n) {
    int g = blockIdx.x;
    int tid = threadIdx.x;
    int lo = 0, hi = n;
    while (lo < hi) { int m = (lo + hi) >> 1; if (batch[m] < g) lo = m + 1; else hi = m; }
    int s0 = lo;
    hi = n;
    while (lo < hi) { int m = (lo + hi) >> 1; if (batch[m] <= g) lo = m + 1; else hi = m; }
    int s1 = lo;
    float4 acc = make_float4(0.f, 0.f, 0.f, 0.f);
    const float4* X = (const float4*)d_x2;
    for (int i = s0; i < s1; ++i) {
        float4 u = X[(size_t)i * 256 + tid];
        acc.x += u.x; acc.y += u.y; acc.z += u.z; acc.w += u.w;
    }
    int c = s1 - s0;
    float inv = 1.f / (float)(c > 0 ? c : 1);
    ((float4*)d_pooled)[g * 256 + tid] =
        make_float4(acc.x * inv, acc.y * inv, acc.z * inv, acc.w * inv);
}

// ---------------- small MLP head ---------------------------------------------
__global__ void k_mlp1(const float* __restrict__ W, const float* __restrict__ bias) {
    __shared__ float sp[1024];
    const int Kd = 1024, Nd = 1024;
    int g = blockIdx.x, tid = threadIdx.x;
    for (int k = tid; k < Kd; k += 256) sp[k] = d_pooled[(size_t)g * Kd + k];
    __syncthreads();
    float acc[4];
#pragma unroll
    for (int s = 0; s < 4; ++s) acc[s] = bias[tid + s * 256];
    for (int k = 0; k < Kd; ++k) {
        float pk = sp[k];
#pragma unroll
        for (int s = 0; s < 4; ++s)
            acc[s] += pk * W[(size_t)k * Nd + tid + s * 256];
    }
#pragma unroll
    for (int s = 0; s < 4; ++s)
        d_hh1[(size_t)g * Nd + tid + s * 256] = fmaxf(acc[s], 0.f);
}

__global__ void k_mlp2(const float* __restrict__ W, const float* __restrict__ bias) {
    __shared__ float sp[1024];
    const int Kd = 1024, Nd = 512;
    int g = blockIdx.x, tid = threadIdx.x;
    for (int k = tid; k < Kd; k += 256) sp[k] = d_hh1[(size_t)g * Kd + k];
    __syncthreads();
    float acc[2];
#pragma unroll
    for (int s = 0; s < 2; ++s) acc[s] = bias[tid + s * 256];
    for (int k = 0; k < Kd; ++k) {
        float pk = sp[k];
#pragma unroll
        for (int s = 0; s < 2; ++s)
            acc[s] += pk * W[(size_t)k * Nd + tid + s * 256];
    }
#pragma unroll
    for (int s = 0; s < 2; ++s)
        d_hh2[(size_t)g * Nd + tid + s * 256] = fmaxf(acc[s], 0.f);
}

__global__ void k_out(const float* __restrict__ oW, const float* __restrict__ ob,
                      float* __restrict__ out, int G) {
    int t = blockIdx.x * blockDim.x + threadIdx.x;
    if (t >= G * 2) return;
    int g = t >> 1, c = t & 1;
    float acc = ob[c];
    for (int k = 0; k < 512; ++k)
        acc += d_hh2[g * 512 + k] * oW[k * 2 + c];
    out[t] = acc;
}

// ---------------- launch ------------------------------------------------------
extern "C" void kernel_launch(void* const* d_in, const int* in_sizes, int n_in,
                              void* d_out, int out_size) {
    const int*   ids   = (const int*)  d_in[0];
    const float* feats = (const float*)d_in[1];
    const int*   eidx  = (const int*)  d_in[2];
    const int*   batch = (const int*)  d_in[3];
    const float* emb   = (const float*)d_in[4];
    const float* W1    = (const float*)d_in[5];
    const float* b1    = (const float*)d_in[6];
    const float* W2    = (const float*)d_in[7];
    const float* b2    = (const float*)d_in[8];
    const float* hW1   = (const float*)d_in[9];
    const float* hb1   = (const float*)d_in[10];
    const float* hW2   = (const float*)d_in[11];
    const float* hb2   = (const float*)d_in[12];
    const float* oW    = (const float*)d_in[13];
    const float* ob    = (const float*)d_in[14];

    int n = in_sizes[0];
    int E = in_sizes[2] / 2;
    int G = out_size / 2;

    const int* src = eidx;
    const int* dst = eidx + E;

    static bool attr_done = false;
    if (!attr_done) {
        cudaFuncSetAttribute(k_gemm2_mma, cudaFuncAttributeMaxDynamicSharedMemorySize,
                             G2_SMEM);
        attr_done = true;
    }

    k_zero_cnt<<<(n + 255) / 256, 256>>>(n);
    k_count<<<(E + 255) / 256, 256>>>(dst, E);
    k_scan<<<1, 1024>>>(n);
    k_scatter<<<(E + 255) / 256, 256>>>(src, dst, E);

    dim3 gp(HID2 / 32, HID1 / 32);
    k_prepB<<<gp, dim3(32, 8)>>>(W2);

    k_agg1<<<(n + 7) / 8, 256>>>(ids, feats, emb, n);

    dim3 g1((n + 127) / 128, HID1 / 64);
    k_gemm1<<<g1, 256>>>(W1, b1, n);

    dim3 g2(HID2 / 128, (n + 127) / 128);   // x = N-block (fast), y = M-block
    k_gemm2_mma<<<g2, 256, G2_SMEM>>>(n);

    k_agg2<<<n, 256>>>(b2, n);

    k_pool<<<G, 256>>>(batch, n);

    k_mlp1<<<G, 256>>>(hW1, hb1);
    k_mlp2<<<G, 256>>>(hW2, hb2);

    k_out<<<1, 128>>>(oW, ob, (float*)d_out, G);
}

// round 6
// speedup vs baseline: 3.2130x; 1.0477x over previous
#include <cuda_runtime.h>
#include <cuda_fp16.h>
#include <stdint.h>

// Problem constants
#define NMAX 20000
#define NPAD 20096           // padded rows (multiple of 128) for tile OOB safety
#define EMAX 160000
#define GMAX 64
#define DIN  36              // 32 emb + 4 feats
#define KP1  64              // padded K for GEMM1 (cols 36..63 stay zero)
#define HID1 2048
#define HID2 1024

// ---------------- scratch (device globals, no runtime alloc) ----------------
__device__ float d_dinv[NMAX];
__device__ int   d_cnt[NMAX];
__device__ int   d_off[NMAX + 1];
__device__ int   d_cur[NMAX];
__device__ int   d_ssrc[EMAX];
__device__ __half d_aggxh[(size_t)NPAD * KP1];   // fp16 aggregated input, zero-padded K
__device__ __half d_w1t[(size_t)HID1 * KP1];     // W1^T fp16 [n][k], zero-padded K
__device__ __half d_h1h[(size_t)NPAD * HID1];    // 41 MB fp16 h1
__device__ __half d_w2t[(size_t)HID2 * HID1];    // 4 MB, [N][K] fp16
__device__ __half d_yh[(size_t)NMAX * HID2];     // 41 MB fp16 y
__device__ __half d_x2h[(size_t)NMAX * HID2];    // 41 MB fp16 x2
__device__ float d_pooled[GMAX * HID2];
__device__ float d_hh1[GMAX * 1024];
__device__ float d_hh2[GMAX * 512];

// ---------------- PTX helpers (base ISA: sm_80+, valid on sm_103) -----------
__device__ __forceinline__ uint32_t smem_to_u32(const void* p) {
    uint32_t a;
    asm("{ .reg .u64 t; cvta.to.shared.u64 t, %1; cvt.u32.u64 %0, t; }" : "=r"(a) : "l"(p));
    return a;
}

#define CP_ASYNC16(dst, src, sz) \
    asm volatile("cp.async.cg.shared.global [%0], [%1], 16, %2;" \
        :: "r"(dst), "l"(src), "r"(sz) : "memory")
#define CP_COMMIT()  asm volatile("cp.async.commit_group;" ::: "memory")
#define CP_WAIT0()   asm volatile("cp.async.wait_group 0;" ::: "memory")

#define LDM_X4(r0, r1, r2, r3, addr) \
    asm volatile("ldmatrix.sync.aligned.m8n8.x4.shared.b16 {%0,%1,%2,%3}, [%4];" \
        : "=r"(r0), "=r"(r1), "=r"(r2), "=r"(r3) : "r"(addr))

#define MMA_FP16(c, a, b0v, b1v) \
    asm volatile("mma.sync.aligned.m16n8k16.row.col.f32.f16.f16.f32 " \
        "{%0,%1,%2,%3},{%4,%5,%6,%7},{%8,%9},{%0,%1,%2,%3};" \
        : "+f"((c)[0]), "+f"((c)[1]), "+f"((c)[2]), "+f"((c)[3]) \
        : "r"((a)[0]), "r"((a)[1]), "r"((a)[2]), "r"((a)[3]), "r"(b0v), "r"(b1v))

// ---------------- CSR build ----------------
__global__ void k_zero_cnt(int n) {
    int i = blockIdx.x * blockDim.x + threadIdx.x;
    if (i < n) d_cnt[i] = 0;
}

__global__ void k_count(const int* __restrict__ dst, int E) {
    int e = blockIdx.x * blockDim.x + threadIdx.x;
    if (e < E) atomicAdd(&d_cnt[dst[e]], 1);
}

__global__ void k_scan(int n) {
    __shared__ int sh[1024];
    __shared__ int carry;
    if (threadIdx.x == 0) carry = 0;
    __syncthreads();
    for (int base = 0; base < n; base += 1024) {
        int i = base + threadIdx.x;
        int v = (i < n) ? d_cnt[i] : 0;
        sh[threadIdx.x] = v;
        __syncthreads();
        for (int s = 1; s < 1024; s <<= 1) {
            int t = (threadIdx.x >= s) ? sh[threadIdx.x - s] : 0;
            __syncthreads();
            sh[threadIdx.x] += t;
            __syncthreads();
        }
        int inc = sh[threadIdx.x];
        if (i < n) {
            int o = carry + inc - v;
            d_off[i] = o;
            d_cur[i] = o;
            d_dinv[i] = rsqrtf((float)(v + 1));
        }
        __syncthreads();
        if (threadIdx.x == 1023) carry += sh[1023];
        __syncthreads();
    }
    if (threadIdx.x == 0) d_off[n] = carry;
}

__global__ void k_scatter(const int* __restrict__ src, const int* __restrict__ dst, int E) {
    int e = blockIdx.x * blockDim.x + threadIdx.x;
    if (e < E) {
        int d = dst[e];
        int p = atomicAdd(&d_cur[d], 1);
        d_ssrc[p] = src[e];
    }
}

// ---------------- layer-1 aggregation in 36-dim space -> fp16 ---------------
__global__ void k_agg1(const int* __restrict__ ids, const float* __restrict__ feats,
                       const float* __restrict__ emb, int n) {
    int w = (blockIdx.x * blockDim.x + threadIdx.x) >> 5;
    int lane = threadIdx.x & 31;
    if (w >= n) return;
    int i = w;
    float di = d_dinv[i];
    float a0 = di * emb[(size_t)ids[i] * 32 + lane];
    float a1 = (lane < 4) ? di * feats[(size_t)i * 4 + lane] : 0.f;
    int e0 = d_off[i], e1 = d_off[i + 1];
    for (int e = e0; e < e1; ++e) {
        int s = d_ssrc[e];
        float c = d_dinv[s];
        a0 += c * emb[(size_t)ids[s] * 32 + lane];
        if (lane < 4) a1 += c * feats[(size_t)s * 4 + lane];
    }
    d_aggxh[(size_t)i * KP1 + lane] = __float2half_rn(di * a0);
    if (lane < 4) d_aggxh[(size_t)i * KP1 + 32 + lane] = __float2half_rn(di * a1);
    // cols 36..63 remain zero (never written; device globals are zero-init)
}

// ---------------- prep W1: [36][2048] fp32 -> W1^T fp16 [2048][64] ----------
__global__ void k_prepW1(const float* __restrict__ W1) {
    int idx = blockIdx.x * 256 + threadIdx.x;   // 36*2048 = 73728 = 288*256
    int n = idx & (HID1 - 1);
    int k = idx >> 11;
    d_w1t[(size_t)n * KP1 + k] = __float2half_rn(W1[(size_t)k * HID1 + n]);
}

// ---------------- prep W2: [K,N] fp32 -> W2^T [N,K] fp16 --------------------
__global__ void k_prepB(const float* __restrict__ W2) {
    __shared__ float t[32][33];
    int nt = blockIdx.x * 32, kt = blockIdx.y * 32;
    int x = threadIdx.x, y = threadIdx.y;
#pragma unroll
    for (int j = 0; j < 4; ++j)
        t[y + j * 8][x] = W2[(size_t)(kt + y + j * 8) * HID2 + nt + x];
    __syncthreads();
#pragma unroll
    for (int j = 0; j < 4; ++j) {
        float v = t[x][y + j * 8];
        d_w2t[(size_t)(nt + y + j * 8) * HID1 + kt + x] = __float2half_rn(v);
    }
}

// ---------------- GEMM1 via mma.sync fp16: h1 = relu(aggx @ W1 + b1) --------
// Tile 128(M) x 128(N), K=64 one shot. 8 warps = 2(m) x 4(n), warp tile 64x32.
// SMEM: A[128][72 halves=144B] | B[128][144B]; 144B rows -> conflict-free ldmatrix.
#define G1_ROWB 144
#define G1_MAT  (128 * G1_ROWB)

__global__ void __launch_bounds__(256) k_gemm1_mma(const float* __restrict__ bias, int M) {
    __shared__ char smem[2 * G1_MAT];
    uint32_t sb = smem_to_u32(smem);
    const int tid = threadIdx.x;
    const int lane = tid & 31, wid = tid >> 5;
    const int wm = wid >> 2, wn = wid & 3;
    const int bn = blockIdx.x * 128;
    const int bm = blockIdx.y * 128;

    // load A (128 x 64 fp16 = 128B rows, 8 x 16B) and B likewise: 2048 chunks
#pragma unroll
    for (int i = 0; i < 4; ++i) {
        int idx = tid + i * 256;            // 0..1023
        int row = idx >> 3, u = idx & 7;
        uint32_t so = (uint32_t)(row * G1_ROWB + u * 16);
        int gr = bm + row;
        int szA = (gr < M) ? 16 : 0;
        CP_ASYNC16(sb + so, (const char*)(d_aggxh + (size_t)gr * KP1 + u * 8), szA);
        CP_ASYNC16(sb + G1_MAT + so,
                   (const char*)(d_w1t + (size_t)(bn + row) * KP1 + u * 8), 16);
    }
    CP_COMMIT();

    float acc[4][4][4];
#pragma unroll
    for (int i = 0; i < 4; ++i)
#pragma unroll
        for (int j = 0; j < 4; ++j)
#pragma unroll
            for (int q = 0; q < 4; ++q) acc[i][j][q] = 0.f;

    CP_WAIT0();
    __syncthreads();

    const int lr = lane & 7;
    const int lm = lane >> 3;

    // B fragments: two x4 loads per nt cover k=0..31 and k=32..63
    uint32_t bf[4][8];
#pragma unroll
    for (int nt = 0; nt < 4; ++nt) {
        uint32_t baddr = sb + G1_MAT +
            (uint32_t)((wn * 32 + nt * 8 + lr) * G1_ROWB + lm * 16);
        LDM_X4(bf[nt][0], bf[nt][1], bf[nt][2], bf[nt][3], baddr);
        LDM_X4(bf[nt][4], bf[nt][5], bf[nt][6], bf[nt][7], baddr + 64);
    }

#pragma unroll
    for (int ks = 0; ks < 4; ++ks) {
        uint32_t af[4][4];
#pragma unroll
        for (int mt = 0; mt < 4; ++mt) {
            uint32_t aaddr = sb +
                (uint32_t)((wm * 64 + mt * 16 + (lm & 1) * 8 + lr) * G1_ROWB +
                           ks * 32 + (lm >> 1) * 16);
            LDM_X4(af[mt][0], af[mt][1], af[mt][2], af[mt][3], aaddr);
        }
#pragma unroll
        for (int mt = 0; mt < 4; ++mt)
#pragma unroll
            for (int nt = 0; nt < 4; ++nt)
                MMA_FP16(acc[mt][nt], af[mt], bf[nt][2 * ks], bf[nt][2 * ks + 1]);
    }

    // epilogue: bias + relu -> fp16
    int r0 = lane >> 2;
    int c0 = (lane & 3) * 2;
#pragma unroll
    for (int nt = 0; nt < 4; ++nt) {
        int gcol = bn + wn * 32 + nt * 8 + c0;
        float b0 = bias[gcol], b1 = bias[gcol + 1];
#pragma unroll
        for (int mt = 0; mt < 4; ++mt) {
            int grow = bm + wm * 64 + mt * 16 + r0;
            if (grow < M)
                *(__half2*)(d_h1h + (size_t)grow * HID1 + gcol) =
                    __floats2half2_rn(fmaxf(acc[mt][nt][0] + b0, 0.f),
                                      fmaxf(acc[mt][nt][1] + b1, 0.f));
            if (grow + 8 < M)
                *(__half2*)(d_h1h + (size_t)(grow + 8) * HID1 + gcol) =
                    __floats2half2_rn(fmaxf(acc[mt][nt][2] + b0, 0.f),
                                      fmaxf(acc[mt][nt][3] + b1, 0.f));
        }
    }
}

// ---------------- GEMM2 via mma.sync fp16: y = h1 @ W2 -> fp16 --------------
#define G2_ROWB   80
#define G2_MAT    (128 * G2_ROWB)
#define G2_BUF    (2 * G2_MAT)
#define G2_SMEM   (2 * G2_BUF)

__global__ void __launch_bounds__(256, 2) k_gemm2_mma(int M) {
    extern __shared__ char smem[];
    uint32_t sb = smem_to_u32(smem);
    const int tid = threadIdx.x;
    const int lane = tid & 31, wid = tid >> 5;
    const int wm = wid >> 2, wn = wid & 3;
    const int bn = blockIdx.x * 128;
    const int bm = blockIdx.y * 128;

    const int NCHUNK = HID1 / 32;   // 64

    auto fill = [&](int buf, int kt) {
        uint32_t base = sb + buf * G2_BUF;
#pragma unroll
        for (int i = 0; i < 2; ++i) {
            int idx = tid + i * 256;
            int row = idx >> 2;
            int u = idx & 3;
            uint32_t so = (uint32_t)(row * G2_ROWB + u * 16);
            int gr = bm + row;
            int szA = (gr < M) ? 16 : 0;
            CP_ASYNC16(base + so, (const char*)(d_h1h + (size_t)gr * HID1 + kt + u * 8), szA);
            CP_ASYNC16(base + G2_MAT + so,
                       (const char*)(d_w2t + (size_t)(bn + row) * HID1 + kt + u * 8), 16);
        }
    };

    float acc[4][4][4];
#pragma unroll
    for (int i = 0; i < 4; ++i)
#pragma unroll
        for (int j = 0; j < 4; ++j)
#pragma unroll
            for (int q = 0; q < 4; ++q) acc[i][j][q] = 0.f;

    fill(0, 0);
    CP_COMMIT();
    CP_WAIT0();
    __syncthreads();

    const int lr = lane & 7;
    const int lm = lane >> 3;

    for (int c = 0; c < NCHUNK; ++c) {
        if (c + 1 < NCHUNK) {
            fill((c + 1) & 1, (c + 1) * 32);
            CP_COMMIT();
        }
        uint32_t base = sb + (c & 1) * G2_BUF;

        uint32_t bf[4][4];
#pragma unroll
        for (int nt = 0; nt < 4; ++nt) {
            uint32_t baddr = base + G2_MAT +
                (uint32_t)((wn * 32 + nt * 8 + lr) * G2_ROWB + lm * 16);
            LDM_X4(bf[nt][0], bf[nt][1], bf[nt][2], bf[nt][3], baddr);
        }

#pragma unroll
        for (int ks = 0; ks < 2; ++ks) {
            uint32_t af[4][4];
#pragma unroll
            for (int mt = 0; mt < 4; ++mt) {
                uint32_t aaddr = base +
                    (uint32_t)((wm * 64 + mt * 16 + (lm & 1) * 8 + lr) * G2_ROWB +
                               ks * 32 + (lm >> 1) * 16);
                LDM_X4(af[mt][0], af[mt][1], af[mt][2], af[mt][3], aaddr);
            }
#pragma unroll
            for (int mt = 0; mt < 4; ++mt)
#pragma unroll
                for (int nt = 0; nt < 4; ++nt)
                    MMA_FP16(acc[mt][nt], af[mt], bf[nt][2 * ks], bf[nt][2 * ks + 1]);
        }
        CP_WAIT0();
        __syncthreads();
    }

    // epilogue: fp16 y
    int r0 = lane >> 2;
    int c0 = (lane & 3) * 2;
#pragma unroll
    for (int mt = 0; mt < 4; ++mt) {
#pragma unroll
        for (int nt = 0; nt < 4; ++nt) {
            int grow = bm + wm * 64 + mt * 16 + r0;
            int gcol = bn + wn * 32 + nt * 8 + c0;
            if (grow < M)
                *(__half2*)(d_yh + (size_t)grow * HID2 + gcol) =
                    __floats2half2_rn(acc[mt][nt][0], acc[mt][nt][1]);
            if (grow + 8 < M)
                *(__half2*)(d_yh + (size_t)(grow + 8) * HID2 + gcol) =
                    __floats2half2_rn(acc[mt][nt][2], acc[mt][nt][3]);
        }
    }
}

// ---------------- layer-2 aggregation + bias + relu (fp16 in/out) -----------
__global__ void k_agg2(const float* __restrict__ b2, int n) {
    int i = blockIdx.x;
    int tid = threadIdx.x;            // 256 threads x 4 halves = 1024 dims
    float di = d_dinv[i];
    const uint2* Y = (const uint2*)d_yh;
    uint2 raw = Y[(size_t)i * 256 + tid];
    float2 p0 = __half22float2(*(__half2*)&raw.x);
    float2 p1 = __half22float2(*(__half2*)&raw.y);
    float c0 = di * di;
    float4 acc = make_float4(p0.x * c0, p0.y * c0, p1.x * c0, p1.y * c0);
    int e0 = d_off[i], e1 = d_off[i + 1];
    for (int e = e0; e < e1; ++e) {
        int s = d_ssrc[e];
        float c = di * d_dinv[s];
        uint2 u = Y[(size_t)s * 256 + tid];
        float2 q0 = __half22float2(*(__half2*)&u.x);
        float2 q1 = __half22float2(*(__half2*)&u.y);
        acc.x += c * q0.x;
        acc.y += c * q0.y;
        acc.z += c * q1.x;
        acc.w += c * q1.y;
    }
    float4 bb = ((const float4*)b2)[tid];
    uint2 out;
    *(__half2*)&out.x = __floats2half2_rn(fmaxf(acc.x + bb.x, 0.f),
                                          fmaxf(acc.y + bb.y, 0.f));
    *(__half2*)&out.y = __floats2half2_rn(fmaxf(acc.z + bb.z, 0.f),
                                          fmaxf(acc.w + bb.w, 0.f));
    ((uint2*)d_x2h)[(size_t)i * 256 + tid] = out;
}

// ---------------- mean pool per graph (batch sorted, fp16 in) ---------------
__global__ void k_pool(const int* __restrict__ batch, int n) {
    int g = blockIdx.x;
    int tid = threadIdx.x;
    int lo = 0, hi = n;
    while (lo < hi) { int m = (lo + hi) >> 1; if (batch[m] < g) lo = m + 1; else hi = m; }
    int s0 = lo;
    hi = n;
    while (lo < hi) { int m = (lo + hi) >> 1; if (batch[m] <= g) lo = m + 1; else hi = m; }
    int s1 = lo;
    float4 acc = make_float4(0.f, 0.f, 0.f, 0.f);
    const uint2* X = (const uint2*)d_x2h;
    for (int i = s0; i < s1; ++i) {
        uint2 u = X[(size_t)i * 256 + tid];
        float2 q0 = __half22float2(*(__half2*)&u.x);
        float2 q1 = __half22float2(*(__half2*)&u.y);
        acc.x += q0.x; acc.y += q0.y; acc.z += q1.x; acc.w += q1.y;
    }
    int c = s1 - s0;
    float inv = 1.f / (float)(c > 0 ? c : 1);
    ((float4*)d_pooled)[g * 256 + tid] =
        make_float4(acc.x * inv, acc.y * inv, acc.z * inv, acc.w * inv);
}

// ---------------- small MLP head (parallelized over column chunks) ----------
__global__ void k_mlp1(const float* __restrict__ W, const float* __restrict__ bias) {
    __shared__ float sp[1024];
    const int Kd = 1024, Nd = 1024;
    int g = blockIdx.x, cq = blockIdx.y, tid = threadIdx.x;
    for (int k = tid; k < Kd; k += 256) sp[k] = d_pooled[(size_t)g * Kd + k];
    __syncthreads();
    int c = cq * 256 + tid;
    float acc = bias[c];
#pragma unroll 4
    for (int k = 0; k < Kd; ++k)
        acc += sp[k] * W[(size_t)k * Nd + c];
    d_hh1[(size_t)g * Nd + c] = fmaxf(acc, 0.f);
}

__global__ void k_mlp2(const float* __restrict__ W, const float* __restrict__ bias) {
    __shared__ float sp[1024];
    const int Kd = 1024, Nd = 512;
    int g = blockIdx.x, cq = blockIdx.y, tid = threadIdx.x;
    for (int k = tid; k < Kd; k += 256) sp[k] = d_hh1[(size_t)g * Kd + k];
    __syncthreads();
    int c = cq * 256 + tid;
    float acc = bias[c];
#pragma unroll 4
    for (int k = 0; k < Kd; ++k)
        acc += sp[k] * W[(size_t)k * Nd + c];
    d_hh2[(size_t)g * Nd + c] = fmaxf(acc, 0.f);
}

__global__ void k_out(const float* __restrict__ oW, const float* __restrict__ ob,
                      float* __restrict__ out, int G) {
    int t = blockIdx.x * blockDim.x + threadIdx.x;
    if (t >= G * 2) return;
    int g = t >> 1, c = t & 1;
    float acc = ob[c];
    for (int k = 0; k < 512; ++k)
        acc += d_hh2[g * 512 + k] * oW[k * 2 + c];
    out[t] = acc;
}

// ---------------- launch ------------------------------------------------------
extern "C" void kernel_launch(void* const* d_in, const int* in_sizes, int n_in,
                              void* d_out, int out_size) {
    const int*   ids   = (const int*)  d_in[0];
    const float* feats = (const float*)d_in[1];
    const int*   eidx  = (const int*)  d_in[2];
    const int*   batch = (const int*)  d_in[3];
    const float* emb   = (const float*)d_in[4];
    const float* W1    = (const float*)d_in[5];
    const float* b1    = (const float*)d_in[6];
    const float* W2    = (const float*)d_in[7];
    const float* b2    = (const float*)d_in[8];
    const float* hW1   = (const float*)d_in[9];
    const float* hb1   = (const float*)d_in[10];
    const float* hW2   = (const float*)d_in[11];
    const float* hb2   = (const float*)d_in[12];
    const float* oW    = (const float*)d_in[13];
    const float* ob    = (const float*)d_in[14];

    int n = in_sizes[0];
    int E = in_sizes[2] / 2;
    int G = out_size / 2;

    const int* src = eidx;
    const int* dst = eidx + E;

    static bool attr_done = false;
    if (!attr_done) {
        cudaFuncSetAttribute(k_gemm2_mma, cudaFuncAttributeMaxDynamicSharedMemorySize,
                             G2_SMEM);
        attr_done = true;
    }

    k_zero_cnt<<<(n + 255) / 256, 256>>>(n);
    k_count<<<(E + 255) / 256, 256>>>(dst, E);
    k_scan<<<1, 1024>>>(n);
    k_scatter<<<(E + 255) / 256, 256>>>(src, dst, E);

    k_prepW1<<<(DIN * HID1) / 256, 256>>>(W1);
    dim3 gp(HID2 / 32, HID1 / 32);
    k_prepB<<<gp, dim3(32, 8)>>>(W2);

    k_agg1<<<(n + 7) / 8, 256>>>(ids, feats, emb, n);

    dim3 g1(HID1 / 128, (n + 127) / 128);
    k_gemm1_mma<<<g1, 256>>>(b1, n);

    dim3 g2(HID2 / 128, (n + 127) / 128);
    k_gemm2_mma<<<g2, 256, G2_SMEM>>>(n);

    k_agg2<<<n, 256>>>(b2, n);

    k_pool<<<G, 256>>>(batch, n);

    k_mlp1<<<dim3(G, 4), 256>>>(hW1, hb1);
    k_mlp2<<<dim3(G, 2), 256>>>(hW2, hb2);

    k_out<<<1, 128>>>(oW, ob, (float*)d_out, G);
}